// round 2
// baseline (speedup 1.0000x reference)
#include <cuda_runtime.h>
#include <cuda_bf16.h>

#define HDIM  224
#define WDIM  224
#define CDIM  64
#define NM    16
#define HW    (HDIM * WDIM)

// CTA = 32x16 pixel strip (2 adjacent 16x16 patches), 128 threads.
// Each thread owns one float4 pixel-quad; sums all 64 channels in registers
// (warp-loads = 4 full contiguous 128B lines). DCT partials per-thread vs
// __ldg bases, shuffle-reduced over lane bits {0,1,3,4} (bit 2 = patch).
__global__ __launch_bounds__(128)
void msp_dct_kernel(const float* __restrict__ x,
                    const float* __restrict__ bases,
                    float* __restrict__ out) {
    __shared__ float sPart[8 * NM];   // [warp*2 + patch][m]
    __shared__ float sCoef[2 * NM];   // [patch][m]

    const int t    = threadIdx.x;
    const int w0   = blockIdx.x * 32;   // 0..192 step 32
    const int h0   = blockIdx.y * 16;   // 0..208 step 16
    const int b    = blockIdx.z;        // 0..15

    const int row  = t >> 3;            // 0..15 within strip
    const int col4 = (t & 7) * 4;       // 0,4,...,28
    const int warp = t >> 5;            // 0..3
    const int lane = t & 31;

    // ---- phase 1: channel sum, registers only ----
    const float* p = x + (size_t)b * CDIM * HW
                       + (size_t)(h0 + row) * WDIM + (w0 + col4);
    float4 acc = make_float4(0.f, 0.f, 0.f, 0.f);
    #pragma unroll 8
    for (int c = 0; c < CDIM; c++) {
        const float4 v = __ldcs(reinterpret_cast<const float4*>(p + (size_t)c * HW));
        acc.x += v.x; acc.y += v.y; acc.z += v.z; acc.w += v.w;
    }

    // ---- phase 2: per-thread DCT partials for all 16 bases ----
    const int pb = row * 16 + (col4 & 15);   // quad offset within the 16x16 patch
    float part[NM];
    #pragma unroll
    for (int m = 0; m < NM; m++) {
        const float4 bq = __ldg(reinterpret_cast<const float4*>(bases + m * 256 + pb));
        part[m] = acc.x * bq.x + acc.y * bq.y + acc.z * bq.z + acc.w * bq.w;
    }
    // reduce over the 16 lanes of each patch: lane bit 2 selects the patch,
    // so xor-reduce over bits 0,1,3,4 keeps the two patches separate.
    #pragma unroll
    for (int m = 0; m < NM; m++) {
        part[m] += __shfl_xor_sync(0xffffffffu, part[m], 1);
        part[m] += __shfl_xor_sync(0xffffffffu, part[m], 2);
        part[m] += __shfl_xor_sync(0xffffffffu, part[m], 8);
        part[m] += __shfl_xor_sync(0xffffffffu, part[m], 16);
    }
    if (lane == 0 || lane == 4) {
        const int pidx = lane >> 2;
        #pragma unroll
        for (int m = 0; m < NM; m++)
            sPart[(warp * 2 + pidx) * NM + m] = part[m];
    }
    __syncthreads();

    if (t < 32) {
        const int m = t & 15, pidx = t >> 4;
        const float c = sPart[(0 + pidx) * NM + m] + sPart[(2 + pidx) * NM + m]
                      + sPart[(4 + pidx) * NM + m] + sPart[(6 + pidx) * NM + m];
        sCoef[pidx * NM + m] = c * (1.0f / (float)CDIM);
    }
    __syncthreads();

    // ---- phase 3: broadcast writes, one float4 per (m) per thread ----
    const int pidx = col4 >> 4;
    float* obase = out + (size_t)b * NM * HW
                       + (size_t)(h0 + row) * WDIM + (w0 + col4);
    #pragma unroll
    for (int m = 0; m < NM; m++) {
        const float v = sCoef[pidx * NM + m];
        __stcs(reinterpret_cast<float4*>(obase + (size_t)m * HW),
               make_float4(v, v, v, v));
    }
}

extern "C" void kernel_launch(void* const* d_in, const int* in_sizes, int n_in,
                              void* d_out, int out_size) {
    const float* x     = (const float*)d_in[0];
    const float* bases = (const float*)d_in[1];
    float*       out   = (float*)d_out;
    dim3 grid(WDIM / 32, HDIM / 16, 16);   // 7 x 14 x 16 = 1568 CTAs
    msp_dct_kernel<<<grid, 128>>>(x, bases, out);
}

// round 3
// speedup vs baseline: 1.1813x; 1.1813x over previous
#include <cuda_runtime.h>
#include <cuda_bf16.h>

#define PH    16
#define PW    16
#define NM    16
#define HDIM  224
#define WDIM  224
#define CDIM  64
#define HW    (HDIM * WDIM)

// One CTA per (b, ph, pw) 16x16 patch. 256 threads.
// Phase 1: channel mean, thread = (pixel-quad, channel-slice-of-16), pure regs + 4KB smem combine.
// Phase 2: 64 threads compute DCT partials vs __ldg bases (L1-hot), 2-warp shuffle reduce.
// Phase 3: broadcast each coefficient over its footprint, streaming float4 stores.
__global__ __launch_bounds__(256, 6)
void msp_dct_kernel(const float* __restrict__ x,
                    const float* __restrict__ bases,
                    float* __restrict__ out) {
    __shared__ float4 sPart[256];        // partial channel sums
    __shared__ float  sW[2][NM];         // per-warp DCT partials
    __shared__ float  sCoef[NM];         // final coefficients

    const int t  = threadIdx.x;
    const int pw = blockIdx.x;           // 0..13
    const int ph = blockIdx.y;           // 0..13
    const int b  = blockIdx.z;           // 0..15
    const int h0 = ph * PH;
    const int w0 = pw * PW;

    // ---- phase 1: sum over C=64, 4 slices of 16 channels ----
    const int g   = t & 63;              // pixel quad 0..63
    const int pi  = g >> 2;              // row in patch
    const int pj4 = (g & 3) * 4;         // col quad start
    const int csl = t >> 6;              // channel slice 0..3
    {
        const float* p = x + ((size_t)(b * CDIM + csl * 16)) * HW
                           + (size_t)(h0 + pi) * WDIM + (w0 + pj4);
        float4 acc = make_float4(0.f, 0.f, 0.f, 0.f);
        #pragma unroll
        for (int cc = 0; cc < 16; cc++) {
            const float4 v = __ldcs(reinterpret_cast<const float4*>(p + (size_t)cc * HW));
            acc.x += v.x; acc.y += v.y; acc.z += v.z; acc.w += v.w;
        }
        sPart[t] = acc;
    }
    __syncthreads();

    // ---- phase 2: 64 threads -> 16 coefficients ----
    if (t < 64) {
        const float4 a0 = sPart[t];
        const float4 a1 = sPart[t + 64];
        const float4 a2 = sPart[t + 128];
        const float4 a3 = sPart[t + 192];
        float4 m4;
        m4.x = a0.x + a1.x + a2.x + a3.x;
        m4.y = a0.y + a1.y + a2.y + a3.y;
        m4.z = a0.z + a1.z + a2.z + a3.z;
        m4.w = a0.w + a1.w + a2.w + a3.w;

        const int pb = pi * 16 + pj4;    // quad offset in 16x16 patch
        float part[NM];
        #pragma unroll
        for (int m = 0; m < NM; m++) {
            const float4 bq = __ldg(reinterpret_cast<const float4*>(bases + m * 256 + pb));
            part[m] = m4.x * bq.x + m4.y * bq.y + m4.z * bq.z + m4.w * bq.w;
        }
        #pragma unroll
        for (int m = 0; m < NM; m++) {
            #pragma unroll
            for (int off = 16; off; off >>= 1)
                part[m] += __shfl_xor_sync(0xffffffffu, part[m], off);
        }
        if ((t & 31) == 0) {
            const int w = t >> 5;        // 0 or 1
            #pragma unroll
            for (int m = 0; m < NM; m++) sW[w][m] = part[m];
        }
    }
    __syncthreads();
    if (t < NM) sCoef[t] = (sW[0][t] + sW[1][t]) * (1.0f / (float)CDIM);
    __syncthreads();

    // ---- phase 3: broadcast writes, 4 float4 per thread ----
    #pragma unroll
    for (int k = 0; k < 4; k++) {
        const int idx = t + k * 256;     // 0..1023
        const int m   = idx >> 6;        // warp-uniform base index
        const int gg  = idx & 63;
        const int ii  = gg >> 2;
        const int jj  = (gg & 3) * 4;
        const float v = sCoef[m];
        float* o = out + ((size_t)(b * NM + m) * HDIM + (h0 + ii)) * WDIM
                       + (w0 + jj);
        __stcs(reinterpret_cast<float4*>(o), make_float4(v, v, v, v));
    }
}

extern "C" void kernel_launch(void* const* d_in, const int* in_sizes, int n_in,
                              void* d_out, int out_size) {
    const float* x     = (const float*)d_in[0];
    const float* bases = (const float*)d_in[1];
    float*       out   = (float*)d_out;
    dim3 grid(WDIM / PW, HDIM / PH, 16);   // 14 x 14 x 16 = 3136 CTAs
    msp_dct_kernel<<<grid, 256>>>(x, bases, out);
}